// round 8
// baseline (speedup 1.0000x reference)
#include <cuda_runtime.h>
#include <cuda_bf16.h>
#include <cstdint>

// Problem constants (SpaAggregator): B=16384, K=32, N=1e6, F=E=128
#define KNBR 32
#define FDIM 128
#define EDIM 128
#define NTBL 1000000

#define BM    32                 // nodes per CTA -> grid = 512
#define NTHR  256                // 8 warps, 4 nodes per warp
#define ATP   36                 // As_t row stride (floats); 144B = 16B multiple

#define ROWB    512              // bytes per table row (128 f32)
#define CH_ROWS 8                // rows per pipeline chunk
#define CH_B    (CH_ROWS * ROWB) // 4096 bytes per chunk
#define NCHUNK  (KNBR / CH_ROWS) // 4 chunks per node
#define NPW     (BM / 8)         // 4 nodes per warp
#define TOTCH   (NPW * NCHUNK)   // 16 chunks per warp

// smem layout (bytes)
#define SMEM_STAGE 0                           // 8 warps * 2 bufs * 4096 = 65536
#define SMEM_AT    65536                       // 128*36*4 = 18432
#define SMEM_IDX   (65536 + 18432)             // 32*32*4  = 4096
#define SMEM_MBAR  (65536 + 18432 + 4096)      // 16 * 8   = 128
#define SMEM_TOT   (65536 + 18432 + 4096 + 128)

__device__ __forceinline__ unsigned long long ffma2(
    unsigned long long a, unsigned long long b, unsigned long long c)
{
    unsigned long long d;
    asm("fma.rn.f32x2 %0, %1, %2, %3;" : "=l"(d) : "l"(a), "l"(b), "l"(c));
    return d;
}
__device__ __forceinline__ unsigned long long pack2(float x, float y)
{
    unsigned long long r;
    asm("mov.b64 %0, {%1, %2};" : "=l"(r) : "f"(x), "f"(y));
    return r;
}
__device__ __forceinline__ void unpack2(unsigned long long v, float& x, float& y)
{
    asm("mov.b64 {%0, %1}, %2;" : "=f"(x), "=f"(y) : "l"(v));
}
__device__ __forceinline__ uint32_t smem_u32(const void* p)
{
    uint32_t a;
    asm("{ .reg .u64 t; cvta.to.shared.u64 t, %1; cvt.u32.u64 %0, t; }"
        : "=r"(a) : "l"(p));
    return a;
}
__device__ __forceinline__ void mbar_wait(uint32_t mb, uint32_t parity)
{
    asm volatile(
        "{\n\t.reg .pred P;\n"
        "W%=:\n\t"
        "mbarrier.try_wait.parity.acquire.cta.shared::cta.b64 P, [%0], %1, 0x989680;\n\t"
        "@P bra D%=;\n\t"
        "bra W%=;\n"
        "D%=:\n\t}"
        :: "r"(mb), "r"(parity) : "memory");
}

// ---------------------------------------------------------------------------
// Gather via async-proxy bulk copies (bypasses L1tex miss-queue cap):
//   each warp: 4 nodes x 4 chunks(8 rows x 512B), double-buffered smem stage,
//   mbarrier expect_tx completion, LDS reduce, k-major As_t store.
// Then FFMA2 GEMM vs W (L1/L2) + bias.
// ---------------------------------------------------------------------------
__global__ __launch_bounds__(NTHR, 2) void spa_tma_kernel(
    const float* __restrict__ table,   // [N, 128]
    const float* __restrict__ W,       // [128, 128]
    const float* __restrict__ bias,    // [128]
    const int*   __restrict__ idx,     // [B, 32] int32
    float*       __restrict__ out,     // [B, 128]
    int B)
{
    extern __shared__ char smem[];
    const uint32_t sbase = smem_u32(smem);
    float* As_t = reinterpret_cast<float*>(smem + SMEM_AT);   // [128][ATP]
    int*   sidx = reinterpret_cast<int*>  (smem + SMEM_IDX);  // [32][32]

    const int tid   = threadIdx.x;
    const int lane  = tid & 31;
    const int warp  = tid >> 5;
    const int blk_m = blockIdx.x * BM;

    // --- init 16 mbarriers (count=1 arrive + tx bytes) ----------------------
    if (tid < 16) {
        asm volatile("mbarrier.init.shared.b64 [%0], %1;"
                     :: "r"(sbase + SMEM_MBAR + tid * 8), "r"(1) : "memory");
    }
    // --- stage indices: 1024 ints, int4 per thread --------------------------
    {
        const int4* ip = reinterpret_cast<const int4*>(idx + (size_t)blk_m * KNBR);
        int4 v = ip[tid];
        v.x = min(max(v.x, 0), NTBL - 1);
        v.y = min(max(v.y, 0), NTBL - 1);
        v.z = min(max(v.z, 0), NTBL - 1);
        v.w = min(max(v.w, 0), NTBL - 1);
        reinterpret_cast<int4*>(sidx)[tid] = v;
    }
    __syncthreads();

    // =============== gather + mean via bulk-async pipeline ==================
    {
        const uint32_t stage0 = sbase + SMEM_STAGE + warp * 2 * CH_B;
        const uint32_t mbar0  = sbase + SMEM_MBAR + warp * 2 * 8;
        int ph0 = 0, ph1 = 0;

        // issue chunk c into buffer (c&1)
        auto issue = [&](int c) {
            const int b    = c & 1;
            const int node = warp * NPW + (c >> 2);
            const int k0   = (c & 3) * CH_ROWS;
            const uint32_t dst = stage0 + b * CH_B;
            const uint32_t mb  = mbar0 + b * 8;
            if (lane == 0)
                asm volatile("mbarrier.arrive.expect_tx.shared.b64 _, [%0], %1;"
                             :: "r"(mb), "r"(CH_B) : "memory");
            __syncwarp();
            if (lane < CH_ROWS) {
                const int r = sidx[node * KNBR + k0 + lane];
                const char* src = reinterpret_cast<const char*>(table) + (size_t)r * ROWB;
                asm volatile(
                    "cp.async.bulk.shared::cluster.global.mbarrier::complete_tx::bytes "
                    "[%0], [%1], %2, [%3];"
                    :: "r"(dst + lane * ROWB), "l"(src), "r"(ROWB), "r"(mb) : "memory");
            }
        };

        issue(0);
        float4 acc = make_float4(0.f, 0.f, 0.f, 0.f);
        #pragma unroll 1
        for (int c = 0; c < TOTCH; ++c) {
            const int b = c & 1;
            if (c + 1 < TOTCH) issue(c + 1);
            // wait chunk c
            if (b == 0) { mbar_wait(mbar0, ph0);     ph0 ^= 1; }
            else        { mbar_wait(mbar0 + 8, ph1); ph1 ^= 1; }
            // reduce 8 rows, lane owns 16B column
            const float4* sp = reinterpret_cast<const float4*>(
                smem + SMEM_STAGE + (warp * 2 + b) * CH_B) + lane;
            #pragma unroll
            for (int r = 0; r < CH_ROWS; ++r) {
                const float4 v = sp[r * 32];
                acc.x += v.x; acc.y += v.y; acc.z += v.z; acc.w += v.w;
            }
            if ((c & (NCHUNK - 1)) == NCHUNK - 1) {      // node complete
                const int ln = warp * NPW + (c >> 2);
                const float s = 1.0f / (float)KNBR;
                float* basep = As_t + (4 * lane) * ATP + ln;   // k-major store
                basep[0 * ATP] = acc.x * s;
                basep[1 * ATP] = acc.y * s;
                basep[2 * ATP] = acc.z * s;
                basep[3 * ATP] = acc.w * s;
                acc = make_float4(0.f, 0.f, 0.f, 0.f);
            }
        }
    }
    __syncthreads();   // As_t ready

    // =============== GEMM: out[32][128] = As^T @ W + bias ===================
    // warp ty handles rows ty*4..+3 (2 packed pairs); lane tx cols tx*4..+3.
    // A-pair load: As_t + k*ATP + ty*4 -> byte offset k*144 + ty*16, 16B-aligned.
    {
        const int tx = lane, ty = warp;
        unsigned long long acc2[2][4];
        #pragma unroll
        for (int p = 0; p < 2; ++p)
            #pragma unroll
            for (int j = 0; j < 4; ++j) acc2[p][j] = 0ull;

        const float4* wp = reinterpret_cast<const float4*>(W) + tx;

        #pragma unroll 8
        for (int k = 0; k < FDIM; ++k) {
            const float4 bv = __ldg(wp + k * 32);
            const ulonglong2 av = *reinterpret_cast<const ulonglong2*>(
                As_t + k * ATP + ty * 4);
            unsigned long long b2[4];
            b2[0] = pack2(bv.x, bv.x);
            b2[1] = pack2(bv.y, bv.y);
            b2[2] = pack2(bv.z, bv.z);
            b2[3] = pack2(bv.w, bv.w);
            #pragma unroll
            for (int j = 0; j < 4; ++j) {
                acc2[0][j] = ffma2(av.x, b2[j], acc2[0][j]);
                acc2[1][j] = ffma2(av.y, b2[j], acc2[1][j]);
            }
        }

        const float4 bb = *reinterpret_cast<const float4*>(bias + tx * 4);
        #pragma unroll
        for (int p = 0; p < 2; ++p) {
            const int m0 = blk_m + ty * 4 + 2 * p;
            float4 o0, o1;
            float lo, hi;
            unpack2(acc2[p][0], lo, hi); o0.x = lo + bb.x; o1.x = hi + bb.x;
            unpack2(acc2[p][1], lo, hi); o0.y = lo + bb.y; o1.y = hi + bb.y;
            unpack2(acc2[p][2], lo, hi); o0.z = lo + bb.z; o1.z = hi + bb.z;
            unpack2(acc2[p][3], lo, hi); o0.w = lo + bb.w; o1.w = hi + bb.w;
            *reinterpret_cast<float4*>(out + (size_t)m0 * EDIM + tx * 4)       = o0;
            *reinterpret_cast<float4*>(out + (size_t)(m0 + 1) * EDIM + tx * 4) = o1;
        }
    }
}

// ---------------------------------------------------------------------------
// Launch. Inputs: id2feat f32 [N,128], weight f32 [128,128], bias f32 [128],
// neigh_idx int32 [B,32]. Output f32 [B,128].
// ---------------------------------------------------------------------------
extern "C" void kernel_launch(void* const* d_in, const int* in_sizes, int n_in,
                              void* d_out, int out_size)
{
    const float* id2feat = (const float*)d_in[0];
    const float* weight  = (const float*)d_in[1];
    const float* bias    = (const float*)d_in[2];
    const int*   nidx    = (const int*)d_in[3];
    float*       out     = (float*)d_out;

    const int B = in_sizes[3] / KNBR;

    cudaFuncSetAttribute(spa_tma_kernel,
                         cudaFuncAttributeMaxDynamicSharedMemorySize, SMEM_TOT);
    spa_tma_kernel<<<(B + BM - 1) / BM, NTHR, SMEM_TOT>>>(
        id2feat, weight, bias, nidx, out, B);
}

// round 10
// speedup vs baseline: 1.1120x; 1.1120x over previous
#include <cuda_runtime.h>
#include <cuda_bf16.h>
#include <cstdint>

// Problem constants (SpaAggregator): B=16384, K=32, N=1e6, F=E=128
#define KNBR 32
#define FDIM 128
#define EDIM 128
#define NTBL 1000000

#define BM     32        // nodes per CTA -> grid = 512
#define NTHR   256       // 8 warps: 4 producer + 4 consumer
#define NTILE  4         // pipeline tiles per CTA
#define TNODES 8         // nodes per tile
#define ATP    10        // As_t node-dim stride (floats); k-stride 40B, pair loads 8B-aligned

// smem (bytes): As_t ring 4*128*10*4 = 20480 ; sidx 32*32*4 = 4096
#define SMEM_AT   0
#define SMEM_IDX  20480
#define SMEM_TOT  (20480 + 4096)

__device__ __forceinline__ unsigned long long ffma2(
    unsigned long long a, unsigned long long b, unsigned long long c)
{
    unsigned long long d;
    asm("fma.rn.f32x2 %0, %1, %2, %3;" : "=l"(d) : "l"(a), "l"(b), "l"(c));
    return d;
}
__device__ __forceinline__ unsigned long long add2(
    unsigned long long a, unsigned long long b)
{
    unsigned long long d;
    asm("add.rn.f32x2 %0, %1, %2;" : "=l"(d) : "l"(a), "l"(b));
    return d;
}
__device__ __forceinline__ unsigned long long pack2(float x, float y)
{
    unsigned long long r;
    asm("mov.b64 %0, {%1, %2};" : "=l"(r) : "f"(x), "f"(y));
    return r;
}
__device__ __forceinline__ void unpack2(unsigned long long v, float& x, float& y)
{
    asm("mov.b64 {%0, %1}, %2;" : "=f"(x), "=f"(y) : "l"(v));
}
// L2 evict_last eviction-policy register (created once per thread)
__device__ __forceinline__ unsigned long long mk_policy_el()
{
    unsigned long long p;
    asm("createpolicy.fractional.L2::evict_last.b64 %0, 1.0;" : "=l"(p));
    return p;
}
// table row load: read-only + L2 cache-hint (keep gathered rows for dedup hits)
__device__ __forceinline__ float4 ldg_row_el(const float4* p, unsigned long long pol)
{
    float4 v;
    asm("ld.global.nc.L2::cache_hint.v4.f32 {%0,%1,%2,%3}, [%4], %5;"
        : "=f"(v.x), "=f"(v.y), "=f"(v.z), "=f"(v.w) : "l"(p), "l"(pol));
    return v;
}

// ---------------------------------------------------------------------------
// Warp-specialized fused kernel, 4-stage pipeline:
//   warps 0-3 (producers): gather+mean 8-node tiles -> As_t ring, bar.arrive
//   warps 4-7 (consumers): bar.sync tile, GEMM vs W (L1/L2) + bias, store
// ---------------------------------------------------------------------------
__global__ __launch_bounds__(NTHR, 4) void spa_fused_ws4_kernel(
    const float* __restrict__ table,   // [N, 128]
    const float* __restrict__ W,       // [128, 128]
    const float* __restrict__ bias,    // [128]
    const int*   __restrict__ idx,     // [B, 32] int32
    float*       __restrict__ out,     // [B, 128]
    int B)
{
    extern __shared__ char smem[];
    float* As_t = reinterpret_cast<float*>(smem + SMEM_AT);   // [4][128][ATP]
    int*   sidx = reinterpret_cast<int*>  (smem + SMEM_IDX);  // [32][32]

    const int tid   = threadIdx.x;
    const int lane  = tid & 31;
    const int warp  = tid >> 5;
    const int blk_m = blockIdx.x * BM;

    // --- stage indices: 1024 ints, int4 per thread (all warps) -------------
    {
        const int4* ip = reinterpret_cast<const int4*>(idx + (size_t)blk_m * KNBR);
        int4 v = ip[tid];
        v.x = min(max(v.x, 0), NTBL - 1);
        v.y = min(max(v.y, 0), NTBL - 1);
        v.z = min(max(v.z, 0), NTBL - 1);
        v.w = min(max(v.w, 0), NTBL - 1);
        reinterpret_cast<int4*>(sidx)[tid] = v;
    }
    __syncthreads();

    if (warp < 4) {
        // =============== PRODUCER: gather + mean ===========================
        const unsigned long long pol = mk_policy_el();
        // tile t: nodes [t*8, t*8+8); this warp: 2 nodes per tile.
        #pragma unroll 1
        for (int t = 0; t < NTILE; ++t) {
            float* At = As_t + t * (128 * ATP);
            #pragma unroll 1
            for (int i = 0; i < 2; ++i) {
                const int c  = warp * 2 + i;          // node within tile 0..7
                const int ln = t * TNODES + c;        // local node 0..31
                const int* nix = sidx + ln * KNBR;
                unsigned long long aA0 = 0, aA1 = 0, aB0 = 0, aB1 = 0;
                #pragma unroll
                for (int k = 0; k < KNBR; k += 2) {
                    const float4 v0 = ldg_row_el(reinterpret_cast<const float4*>(
                                          table + (size_t)nix[k] * FDIM) + lane, pol);
                    const float4 v1 = ldg_row_el(reinterpret_cast<const float4*>(
                                          table + (size_t)nix[k + 1] * FDIM) + lane, pol);
                    aA0 = add2(aA0, pack2(v0.x, v0.y));
                    aA1 = add2(aA1, pack2(v0.z, v0.w));
                    aB0 = add2(aB0, pack2(v1.x, v1.y));
                    aB1 = add2(aB1, pack2(v1.z, v1.w));
                }
                float x0, x1, x2, x3, y0, y1, y2, y3;
                unpack2(aA0, x0, x1); unpack2(aA1, x2, x3);
                unpack2(aB0, y0, y1); unpack2(aB1, y2, y3);
                const float s = 1.0f / (float)KNBR;
                float* basep = At + (4 * lane) * ATP + c;   // k-major store
                basep[0 * ATP] = (x0 + y0) * s;
                basep[1 * ATP] = (x1 + y1) * s;
                basep[2 * ATP] = (x2 + y2) * s;
                basep[3 * ATP] = (x3 + y3) * s;
            }
            // signal tile t ready (named barrier t+1, total count 256)
            switch (t) {
                case 0: asm volatile("bar.arrive 1, 256;" ::: "memory"); break;
                case 1: asm volatile("bar.arrive 2, 256;" ::: "memory"); break;
                case 2: asm volatile("bar.arrive 3, 256;" ::: "memory"); break;
                default:asm volatile("bar.arrive 4, 256;" ::: "memory"); break;
            }
        }
    } else {
        // =============== CONSUMER: GEMM + bias + store ======================
        const int w4 = warp - 4;                 // 0..3: nodes w4*2, w4*2+1 of tile
        const int tx = lane;
        const float4* wp = reinterpret_cast<const float4*>(W) + tx;  // W[k][4tx..]
        const float4 bb = *reinterpret_cast<const float4*>(bias + tx * 4);

        #pragma unroll 1
        for (int t = 0; t < NTILE; ++t) {
            switch (t) {
                case 0: asm volatile("bar.sync 1, 256;" ::: "memory"); break;
                case 1: asm volatile("bar.sync 2, 256;" ::: "memory"); break;
                case 2: asm volatile("bar.sync 3, 256;" ::: "memory"); break;
                default:asm volatile("bar.sync 4, 256;" ::: "memory"); break;
            }

            const float* At = As_t + t * (128 * ATP);
            unsigned long long acc2[4];
            #pragma unroll
            for (int j = 0; j < 4; ++j) acc2[j] = 0ull;

            #pragma unroll 8
            for (int k = 0; k < FDIM; ++k) {
                const float4 bv = __ldg(wp + k * 32);
                // a: 2 nodes = 1 packed pair, LDS.64 broadcast (same addr all lanes)
                const unsigned long long av = *reinterpret_cast<const unsigned long long*>(
                    At + k * ATP + w4 * 2);
                acc2[0] = ffma2(av, pack2(bv.x, bv.x), acc2[0]);
                acc2[1] = ffma2(av, pack2(bv.y, bv.y), acc2[1]);
                acc2[2] = ffma2(av, pack2(bv.z, bv.z), acc2[2]);
                acc2[3] = ffma2(av, pack2(bv.w, bv.w), acc2[3]);
            }

            const int m0 = blk_m + t * TNODES + w4 * 2;
            float4 o0, o1;
            float lo, hi;
            unpack2(acc2[0], lo, hi); o0.x = lo + bb.x; o1.x = hi + bb.x;
            unpack2(acc2[1], lo, hi); o0.y = lo + bb.y; o1.y = hi + bb.y;
            unpack2(acc2[2], lo, hi); o0.z = lo + bb.z; o1.z = hi + bb.z;
            unpack2(acc2[3], lo, hi); o0.w = lo + bb.w; o1.w = hi + bb.w;
            *reinterpret_cast<float4*>(out + (size_t)m0 * EDIM + tx * 4)       = o0;
            *reinterpret_cast<float4*>(out + (size_t)(m0 + 1) * EDIM + tx * 4) = o1;
        }
    }
}

// ---------------------------------------------------------------------------
// Launch. Inputs: id2feat f32 [N,128], weight f32 [128,128], bias f32 [128],
// neigh_idx int32 [B,32]. Output f32 [B,128].
// ---------------------------------------------------------------------------
extern "C" void kernel_launch(void* const* d_in, const int* in_sizes, int n_in,
                              void* d_out, int out_size)
{
    const float* id2feat = (const float*)d_in[0];
    const float* weight  = (const float*)d_in[1];
    const float* bias    = (const float*)d_in[2];
    const int*   nidx    = (const int*)d_in[3];
    float*       out     = (float*)d_out;

    const int B = in_sizes[3] / KNBR;

    cudaFuncSetAttribute(spa_fused_ws4_kernel,
                         cudaFuncAttributeMaxDynamicSharedMemorySize, SMEM_TOT);
    spa_fused_ws4_kernel<<<(B + BM - 1) / BM, NTHR, SMEM_TOT>>>(
        id2feat, weight, bias, nidx, out, B);
}

// round 11
// speedup vs baseline: 1.1570x; 1.0405x over previous
#include <cuda_runtime.h>
#include <cuda_bf16.h>
#include <cstdint>

// Problem constants (SpaAggregator): B=16384, K=32, N=1e6, F=E=128
#define KNBR 32
#define FDIM 128
#define EDIM 128
#define NTBL 1000000

#define BM    32         // nodes per CTA -> grid = 512 for B=16384
#define NTHR  256        // 8 warps: 4 producer + 4 consumer
#define TILE  16         // nodes per pipeline tile (2 tiles per CTA)
#define ATP   20         // As_t row stride in floats (16 + pad; 80B, 16B-aligned)

// Dynamic smem (bytes): As_t[2] tiles 2*128*20*4 = 20480 ; sidx 32*32*4 = 4096
#define SMEM_AT   0
#define SMEM_IDX  20480
#define SMEM_TOT  (20480 + 4096)

__device__ __forceinline__ unsigned long long ffma2(
    unsigned long long a, unsigned long long b, unsigned long long c)
{
    unsigned long long d;
    asm("fma.rn.f32x2 %0, %1, %2, %3;" : "=l"(d) : "l"(a), "l"(b), "l"(c));
    return d;
}
__device__ __forceinline__ unsigned long long add2(
    unsigned long long a, unsigned long long b)
{
    unsigned long long d;
    asm("add.rn.f32x2 %0, %1, %2;" : "=l"(d) : "l"(a), "l"(b));
    return d;
}
__device__ __forceinline__ unsigned long long pack2(float x, float y)
{
    unsigned long long r;
    asm("mov.b64 %0, {%1, %2};" : "=l"(r) : "f"(x), "f"(y));
    return r;
}
__device__ __forceinline__ void unpack2(unsigned long long v, float& x, float& y)
{
    asm("mov.b64 {%0, %1}, %2;" : "=f"(x), "=f"(y) : "l"(v));
}
// table row load: L2-only (no L1 allocation; rows have zero L1 reuse)
__device__ __forceinline__ float4 ldg_cg(const float4* p)
{
    float4 v;
    asm("ld.global.cg.v4.f32 {%0,%1,%2,%3}, [%4];"
        : "=f"(v.x), "=f"(v.y), "=f"(v.z), "=f"(v.w) : "l"(p));
    return v;
}
// output store: streaming (evict-first) — don't displace table rows in L2
__device__ __forceinline__ void stg_cs(float4* p, float4 v)
{
    asm volatile("st.global.cs.v4.f32 [%0], {%1,%2,%3,%4};"
                 :: "l"(p), "f"(v.x), "f"(v.y), "f"(v.z), "f"(v.w) : "memory");
}

// ---------------------------------------------------------------------------
// Warp-specialized fused kernel (best-known structure, R6):
//   warps 0-3: gather + mean -> As_t tile ring (k-major), bar.arrive
//   warps 4-7: bar.sync, GEMM tile vs W (L1/L2), +bias, streaming store
// ---------------------------------------------------------------------------
__global__ __launch_bounds__(NTHR, 4) void spa_fused_ws_kernel(
    const float* __restrict__ table,   // [N, 128]
    const float* __restrict__ W,       // [128, 128]
    const float* __restrict__ bias,    // [128]
    const int*   __restrict__ idx,     // [B, 32] int32
    float*       __restrict__ out,     // [B, 128]
    int B)
{
    extern __shared__ char smem[];
    float* As_t = reinterpret_cast<float*>(smem + SMEM_AT);   // [2][128][ATP]
    int*   sidx = reinterpret_cast<int*>  (smem + SMEM_IDX);  // [32][32]

    const int tid   = threadIdx.x;
    const int lane  = tid & 31;
    const int warp  = tid >> 5;
    const int blk_m = blockIdx.x * BM;

    // --- stage indices: 1024 ints, int4 per thread (all warps) -------------
    {
        const int4* ip = reinterpret_cast<const int4*>(idx + (size_t)blk_m * KNBR);
        int4 v = __ldg(ip + tid);
        v.x = min(max(v.x, 0), NTBL - 1);
        v.y = min(max(v.y, 0), NTBL - 1);
        v.z = min(max(v.z, 0), NTBL - 1);
        v.w = min(max(v.w, 0), NTBL - 1);
        reinterpret_cast<int4*>(sidx)[tid] = v;
    }
    __syncthreads();

    if (warp < 4) {
        // =============== PRODUCER: gather + mean ===========================
        // tile t: nodes [t*16, t*16+16); this warp: 4 nodes per tile.
        #pragma unroll 1
        for (int t = 0; t < 2; ++t) {
            float* At = As_t + t * (128 * ATP);
            #pragma unroll 1
            for (int i = 0; i < TILE / 4; ++i) {
                const int c  = warp * 4 + i;          // column within tile
                const int ln = t * TILE + c;          // local node 0..31
                const int* nix = sidx + ln * KNBR;
                unsigned long long aA0 = 0, aA1 = 0, aB0 = 0, aB1 = 0;
                #pragma unroll
                for (int k = 0; k < KNBR; k += 2) {
                    const float4 v0 = ldg_cg(reinterpret_cast<const float4*>(
                                          table + (size_t)nix[k] * FDIM) + lane);
                    const float4 v1 = ldg_cg(reinterpret_cast<const float4*>(
                                          table + (size_t)nix[k + 1] * FDIM) + lane);
                    aA0 = add2(aA0, pack2(v0.x, v0.y));
                    aA1 = add2(aA1, pack2(v0.z, v0.w));
                    aB0 = add2(aB0, pack2(v1.x, v1.y));
                    aB1 = add2(aB1, pack2(v1.z, v1.w));
                }
                float x0, x1, x2, x3, y0, y1, y2, y3;
                unpack2(aA0, x0, x1); unpack2(aA1, x2, x3);
                unpack2(aB0, y0, y1); unpack2(aB1, y2, y3);
                const float s = 1.0f / (float)KNBR;
                float* base = At + (4 * lane) * ATP + c;   // k-major store
                base[0 * ATP] = (x0 + y0) * s;
                base[1 * ATP] = (x1 + y1) * s;
                base[2 * ATP] = (x2 + y2) * s;
                base[3 * ATP] = (x3 + y3) * s;
            }
            // signal tile t ready (barrier id t+1, total count = 256)
            if (t == 0) asm volatile("bar.arrive 1, 256;" ::: "memory");
            else        asm volatile("bar.arrive 2, 256;" ::: "memory");
        }
    } else {
        // =============== CONSUMER: GEMM + bias + store ======================
        const int w4 = warp - 4;                 // 0..3: rows w4*4..+3 of tile
        const int tx = lane;
        const float4* wp = reinterpret_cast<const float4*>(W) + tx;  // W[k][4tx..]
        const float4 bb = *reinterpret_cast<const float4*>(bias + tx * 4);

        #pragma unroll 1
        for (int t = 0; t < 2; ++t) {
            if (t == 0) asm volatile("bar.sync 1, 256;" ::: "memory");
            else        asm volatile("bar.sync 2, 256;" ::: "memory");

            const float* At = As_t + t * (128 * ATP);
            unsigned long long acc2[2][4];
            #pragma unroll
            for (int p = 0; p < 2; ++p)
                #pragma unroll
                for (int j = 0; j < 4; ++j) acc2[p][j] = 0ull;

            #pragma unroll 8
            for (int k = 0; k < FDIM; ++k) {
                const float4 bv = __ldg(wp + k * 32);
                // a: 4 consecutive nodes = 2 packed pairs, one LDS.128 (broadcast)
                const ulonglong2 av = *reinterpret_cast<const ulonglong2*>(
                    At + k * ATP + w4 * 4);
                unsigned long long b2[4];
                b2[0] = pack2(bv.x, bv.x);
                b2[1] = pack2(bv.y, bv.y);
                b2[2] = pack2(bv.z, bv.z);
                b2[3] = pack2(bv.w, bv.w);
                #pragma unroll
                for (int j = 0; j < 4; ++j) {
                    acc2[0][j] = ffma2(av.x, b2[j], acc2[0][j]);
                    acc2[1][j] = ffma2(av.y, b2[j], acc2[1][j]);
                }
            }

            #pragma unroll
            for (int p = 0; p < 2; ++p) {
                const int m0 = blk_m + t * TILE + w4 * 4 + 2 * p;
                float4 o0, o1;
                float lo, hi;
                unpack2(acc2[p][0], lo, hi); o0.x = lo + bb.x; o1.x = hi + bb.x;
                unpack2(acc2[p][1], lo, hi); o0.y = lo + bb.y; o1.y = hi + bb.y;
                unpack2(acc2[p][2], lo, hi); o0.z = lo + bb.z; o1.z = hi + bb.z;
                unpack2(acc2[p][3], lo, hi); o0.w = lo + bb.w; o1.w = hi + bb.w;
                stg_cs(reinterpret_cast<float4*>(out + (size_t)m0 * EDIM + tx * 4), o0);
                stg_cs(reinterpret_cast<float4*>(out + (size_t)(m0 + 1) * EDIM + tx * 4), o1);
            }
        }
    }
}

// ---------------------------------------------------------------------------
// Launch. Inputs: id2feat f32 [N,128], weight f32 [128,128], bias f32 [128],
// neigh_idx int32 [B,32]. Output f32 [B,128].
// ---------------------------------------------------------------------------
extern "C" void kernel_launch(void* const* d_in, const int* in_sizes, int n_in,
                              void* d_out, int out_size)
{
    const float* id2feat = (const float*)d_in[0];
    const float* weight  = (const float*)d_in[1];
    const float* bias    = (const float*)d_in[2];
    const int*   nidx    = (const int*)d_in[3];
    float*       out     = (float*)d_out;

    const int B = in_sizes[3] / KNBR;

    cudaFuncSetAttribute(spa_fused_ws_kernel,
                         cudaFuncAttributeMaxDynamicSharedMemorySize, SMEM_TOT);
    spa_fused_ws_kernel<<<(B + BM - 1) / BM, NTHR, SMEM_TOT>>>(
        id2feat, weight, bias, nidx, out, B);
}